// round 13
// baseline (speedup 1.0000x reference)
#include <cuda_runtime.h>

#define IMG 256
#define NG 1024
#define PIX (1.0f/256.0f)
#define T_TH 1e-4f
#define QCUT 10.0f   // cull: quad > 10 => contribution < alpha*e^-5 (boundary-only)
#define NBLK 256     // 16 x 16 tiles of 16x16 px; all resident in one wave

// Sorted + packed per-Gaussian data (device scratch, no allocs)
__device__ float4 g_cull[NG];  // mx, my, rad2, pad
__device__ float4 g_q[NG];     // c00', c01', c11', k'
__device__ float4 g_c[NG];     // cr, cg, cb, pad
__device__ unsigned long long g_bar;   // monotonic barrier counter (zero-init)

// ---------------------------------------------------------------------------
// Single fused kernel: 256 blocks x 128 threads, 16x16 tile, 2 pixels/thread
// (rows ty and ty+8). Shared LDS + shared dx-terms between the two pixels,
// two independent T-chains -> 2x ILP on the composite critical path.
// Phase 0: each block preps 4 Gaussians (one warp each), device-wide barrier.
// Phase 1: per-tile cull+compact (8 Gaussians/thread).
// Phase 2: dual-pixel front-to-back composite, pipelined groups of 4.
// ---------------------------------------------------------------------------
__global__ void __launch_bounds__(128) fused_kernel(const float* __restrict__ mean,
                                                    const float* __restrict__ cov,
                                                    const float* __restrict__ color,
                                                    const float* __restrict__ alpha,
                                                    const float* __restrict__ depth,
                                                    const float* __restrict__ bg,
                                                    const float* __restrict__ topleft,
                                                    float* __restrict__ out) {
    __shared__ float4 sA[NG+8];        // mx, my, c00', c01'  (aliased by depths in phase 0)
    __shared__ float4 sB[NG+8];        // c11', k', cr, cg
    __shared__ float4 sC4[(NG+8)/4];   // cb, packed
    __shared__ int    sW[4];

    int tid  = threadIdx.x;
    int lane = tid & 31, warp = tid >> 5;

    // tile geometry + background prefetch (hides under barrier wait)
    int bx = blockIdx.x & 15, by = blockIdx.x >> 4;
    float tlx = topleft[0], tly = topleft[1];
    int tx = tid & 15, ty = tid >> 4;          // ty in 0..7; pixels ty and ty+8
    int pi1 = ((by*16 + ty    )*IMG + bx*16 + tx)*3;
    int pi2 = ((by*16 + ty + 8)*IMG + bx*16 + tx)*3;
    float bgr1 = bg[pi1+0], bgg1 = bg[pi1+1], bgb1 = bg[pi1+2];
    float bgr2 = bg[pi2+0], bgg2 = bg[pi2+1], bgb2 = bg[pi2+2];

    // ================= Phase 0: prep (4 Gaussians per block, 1 warp each) ====
    {
        float4* sd4 = (float4*)sA;              // alias: 1024 depths = 4KB
        const float4* d4g = (const float4*)depth;
        sd4[tid]       = d4g[tid];
        sd4[tid + 128] = d4g[tid + 128];
        __syncthreads();

        int gi = blockIdx.x*4 + warp;
        float di = ((const float*)sd4)[gi];
        int r = 0;
        #pragma unroll
        for (int k = 0; k < 8; k++) {
            float4 d = sd4[lane*8 + k];
            int j = (lane*8 + k)*4;
            r += (d.x < di) || (d.x == di && (j+0) < gi);
            r += (d.y < di) || (d.y == di && (j+1) < gi);
            r += (d.z < di) || (d.z == di && (j+2) < gi);
            r += (d.w < di) || (d.w == di && (j+3) < gi);
        }
        #pragma unroll
        for (int s = 16; s; s >>= 1) r += __shfl_xor_sync(0xffffffffu, r, s);

        if (lane == 0) {
            int rank = r;
            float a = cov[gi*4+0], b = cov[gi*4+1], c = cov[gi*4+2], d = cov[gi*4+3];
            float det = a*d - b*c;
            const float L2E = 1.4426950408889634f;
            float i00  = d / det;
            float i11  = a / det;
            float ioff = -(b + c) / det;
            float mx = mean[gi*2+0], my = mean[gi*2+1];
            float bs      = 0.5f*(b + c);
            float half_tr = 0.5f*(a + d);
            float disc    = sqrtf(0.25f*(a - d)*(a - d) + bs*bs);
            float al = alpha[gi];
            g_cull[rank] = make_float4(mx, my, QCUT*(half_tr + disc), 0.0f);
            g_q[rank]    = make_float4(-0.5f*L2E*i00, -0.5f*L2E*ioff, -0.5f*L2E*i11,
                                       __log2f(fmaxf(al, 1e-30f)));
            g_c[rank]    = make_float4(color[gi*3+0], color[gi*3+1], color[gi*3+2], 0.0f);
            __threadfence();                    // release this Gaussian's record
        }
        __syncthreads();

        // device-wide barrier (replay-safe; all blocks resident in one wave)
        if (tid == 0) {
            unsigned long long ticket = atomicAdd(&g_bar, 1ULL);
            unsigned long long target = (ticket/NBLK + 1ULL) * NBLK;
            unsigned long long cur;
            do {
                asm volatile("ld.acquire.gpu.global.u64 %0, [%1];"
                             : "=l"(cur) : "l"(&g_bar));
            } while (cur < target);
        }
        __syncthreads();
    }

    // ================= Phase 1: cull + compact (8 Gaussians/thread) ==========
    float x0 = (bx*16 + 0.5f)*PIX - tlx;
    float x1 = (bx*16 + 15.5f)*PIX - tlx;
    float y0 = (by*16 + 0.5f)*PIX - tly;
    float y1 = (by*16 + 15.5f)*PIX - tly;

    int g0 = tid*8;
    unsigned m = 0;
    #pragma unroll
    for (int u = 0; u < 8; u++) {
        float4 cu = g_cull[g0+u];
        float cx = fminf(fmaxf(cu.x, x0), x1) - cu.x;
        float cy = fminf(fmaxf(cu.y, y0), y1) - cu.y;
        if (cx*cx + cy*cy <= cu.z) m |= (1u << u);
    }
    int cnt = __popc(m);
    int scan = cnt;
    #pragma unroll
    for (int d = 1; d < 32; d <<= 1) {
        int v = __shfl_up_sync(0xffffffffu, scan, d);
        if (lane >= d) scan += v;
    }
    if (lane == 31) sW[warp] = scan;
    __syncthreads();                             // warp totals
    int4 wv = *(const int4*)&sW[0];
    int ntot = wv.x + wv.y + wv.z + wv.w;
    int base = 0;
    if (warp > 0) base += wv.x;
    if (warp > 1) base += wv.y;
    if (warp > 2) base += wv.z;
    int pos = base + (scan - cnt);
    #pragma unroll
    for (int u = 0; u < 8; u++) {
        if (m & (1u << u)) {
            float4 cu = g_cull[g0+u];            // L1-hot reload
            float4 qv = g_q[g0+u];
            float4 cv = g_c[g0+u];
            sA[pos] = make_float4(cu.x, cu.y, qv.x, qv.y);
            sB[pos] = make_float4(qv.z, qv.w, cv.x, cv.y);
            ((float*)sC4)[pos] = cv.z;
            pos++;
        }
    }
    if (tid < 8) {                               // zero-alpha dummies (exact no-op)
        sA[ntot+tid] = make_float4(0.f, 0.f, 0.f, 0.f);
        sB[ntot+tid] = make_float4(0.f, -1e30f, 0.f, 0.f);
        ((float*)sC4)[ntot+tid] = 0.f;
    }
    __syncthreads();                             // list published
    int n = (ntot + 3) & ~3;

    // ================= Phase 2: dual-pixel composite =========================
    float px  = (bx*16 + tx + 0.5f)*PIX - tlx;
    float py1 = (by*16 + ty + 0.5f)*PIX - tly;
    float py2 = py1 + 8.0f*PIX;

    float T1 = 1.0f, cr1 = 0.0f, cg1 = 0.0f, cb1 = 0.0f;
    float T2 = 1.0f, cr2 = 0.0f, cg2 = 0.0f, cb2 = 0.0f;

    float4 A0 = sA[0], A1 = sA[1], A2 = sA[2], A3 = sA[3];
    float4 B0 = sB[0], B1 = sB[1], B2 = sB[2], B3 = sB[3];
    float4 Cv = sC4[0];

    #pragma unroll 2
    for (int i = 0; i < n; i += 4) {
        float4 nA0 = sA[i+4], nA1 = sA[i+5], nA2 = sA[i+6], nA3 = sA[i+7];
        float4 nB0 = sB[i+4], nB1 = sB[i+5], nB2 = sB[i+6], nB3 = sB[i+7];
        float4 nCv = sC4[i/4 + 1];

        float a1[4], a2[4];
        #pragma unroll
        for (int u = 0; u < 4; u++) {
            float4 A = (u==0)?A0:(u==1)?A1:(u==2)?A2:A3;
            float4 B = (u==0)?B0:(u==1)?B1:(u==2)?B2:B3;
            float dx = px - A.x;
            float ta = fmaf(A.z*dx, dx, B.y);    // shared between pixels
            float tb = A.w * dx;                 // shared between pixels
            float dy1 = py1 - A.y;
            float dy2 = py2 - A.y;
            float qd1 = fmaf(dy1, fmaf(B.x, dy1, tb), ta);
            float qd2 = fmaf(dy2, fmaf(B.x, dy2, tb), ta);
            a1[u] = fminf(exp2f(qd1), 0.99f);
            a2[u] = fminf(exp2f(qd2), 0.99f);
        }

        // pixel 1 chain
        {
            float q0 = 1.0f-a1[0], q1 = 1.0f-a1[1], q2 = 1.0f-a1[2], q3 = 1.0f-a1[3];
            float p2 = q0*q1;
            float Tn = T1 * (p2*(q2*q3));
            if (Tn > T_TH) {
                float t0 = T1, t1 = T1*q0, t2 = T1*p2, t3 = t2*q2;
                float w0 = a1[0]*t0, w1 = a1[1]*t1, w2 = a1[2]*t2, w3 = a1[3]*t3;
                cr1 = fmaf(w0, B0.z, cr1); cg1 = fmaf(w0, B0.w, cg1); cb1 = fmaf(w0, Cv.x, cb1);
                cr1 = fmaf(w1, B1.z, cr1); cg1 = fmaf(w1, B1.w, cg1); cb1 = fmaf(w1, Cv.y, cb1);
                cr1 = fmaf(w2, B2.z, cr1); cg1 = fmaf(w2, B2.w, cg1); cb1 = fmaf(w2, Cv.z, cb1);
                cr1 = fmaf(w3, B3.z, cr1); cg1 = fmaf(w3, B3.w, cg1); cb1 = fmaf(w3, Cv.w, cb1);
                T1 = Tn;
            } else if (T1 > T_TH) {
                float rr[4] = {B0.z, B1.z, B2.z, B3.z};
                float gg[4] = {B0.w, B1.w, B2.w, B3.w};
                float bb[4] = {Cv.x, Cv.y, Cv.z, Cv.w};
                #pragma unroll
                for (int u = 0; u < 4; u++) {
                    if (T1 > T_TH) {
                        float w = a1[u] * T1;
                        cr1 = fmaf(w, rr[u], cr1);
                        cg1 = fmaf(w, gg[u], cg1);
                        cb1 = fmaf(w, bb[u], cb1);
                        T1 *= (1.0f - a1[u]);
                    }
                }
            }
        }
        // pixel 2 chain
        {
            float q0 = 1.0f-a2[0], q1 = 1.0f-a2[1], q2 = 1.0f-a2[2], q3 = 1.0f-a2[3];
            float p2 = q0*q1;
            float Tn = T2 * (p2*(q2*q3));
            if (Tn > T_TH) {
                float t0 = T2, t1 = T2*q0, t2 = T2*p2, t3 = t2*q2;
                float w0 = a2[0]*t0, w1 = a2[1]*t1, w2 = a2[2]*t2, w3 = a2[3]*t3;
                cr2 = fmaf(w0, B0.z, cr2); cg2 = fmaf(w0, B0.w, cg2); cb2 = fmaf(w0, Cv.x, cb2);
                cr2 = fmaf(w1, B1.z, cr2); cg2 = fmaf(w1, B1.w, cg2); cb2 = fmaf(w1, Cv.y, cb2);
                cr2 = fmaf(w2, B2.z, cr2); cg2 = fmaf(w2, B2.w, cg2); cb2 = fmaf(w2, Cv.z, cb2);
                cr2 = fmaf(w3, B3.z, cr2); cg2 = fmaf(w3, B3.w, cg2); cb2 = fmaf(w3, Cv.w, cb2);
                T2 = Tn;
            } else if (T2 > T_TH) {
                float rr[4] = {B0.z, B1.z, B2.z, B3.z};
                float gg[4] = {B0.w, B1.w, B2.w, B3.w};
                float bb[4] = {Cv.x, Cv.y, Cv.z, Cv.w};
                #pragma unroll
                for (int u = 0; u < 4; u++) {
                    if (T2 > T_TH) {
                        float w = a2[u] * T2;
                        cr2 = fmaf(w, rr[u], cr2);
                        cg2 = fmaf(w, gg[u], cg2);
                        cb2 = fmaf(w, bb[u], cb2);
                        T2 *= (1.0f - a2[u]);
                    }
                }
            }
        }
        if (T1 <= T_TH && T2 <= T_TH) break;

        A0 = nA0; A1 = nA1; A2 = nA2; A3 = nA3;
        B0 = nB0; B1 = nB1; B2 = nB2; B3 = nB3;
        Cv = nCv;
    }

    out[pi1+0] = cr1 + T1*bgr1;
    out[pi1+1] = cg1 + T1*bgg1;
    out[pi1+2] = cb1 + T1*bgb1;
    out[pi2+0] = cr2 + T2*bgr2;
    out[pi2+1] = cg2 + T2*bgg2;
    out[pi2+2] = cb2 + T2*bgb2;
}

extern "C" void kernel_launch(void* const* d_in, const int* in_sizes, int n_in,
                              void* d_out, int out_size) {
    const float* mean    = (const float*)d_in[0];
    const float* cov     = (const float*)d_in[1];
    const float* color   = (const float*)d_in[2];
    const float* alpha   = (const float*)d_in[3];
    const float* depth   = (const float*)d_in[4];
    const float* bg      = (const float*)d_in[5];
    const float* topleft = (const float*)d_in[6];

    fused_kernel<<<NBLK, 128>>>(mean, cov, color, alpha, depth,
                                bg, topleft, (float*)d_out);
}

// round 14
// speedup vs baseline: 1.1146x; 1.1146x over previous
#include <cuda_runtime.h>

#define IMG 256
#define NG 1024
#define PIX (1.0f/256.0f)
#define T_TH 1e-4f
#define QCUT 10.0f   // cull: quad > 10 => contribution < alpha*e^-5 (boundary-only)
#define NBLK 256     // 16 x 16 tiles of 16x16 px; all resident in one wave

// Sorted + packed per-Gaussian data (device scratch, no allocs)
__device__ float4 g_cull[NG];  // mx, my, rad2, pad
__device__ float4 g_q[NG];     // c00', c01', c11', k'
__device__ float4 g_c[NG];     // cr, cg, cb, pad
__device__ unsigned long long g_bar;   // monotonic barrier counter (zero-init)

// ---------------------------------------------------------------------------
// Single fused kernel: 256 blocks x 256 threads, all resident in one wave.
// Phase 0: each block preps 4 Gaussians, device-wide barrier (replay-safe).
// Phase 1: per-tile cull+compact of all 1024 sorted Gaussians (4 per thread).
// Phase 2: BRANCH-FREE composite: unconditional masked-free updates (error
//          bounded by T<=1e-4 telescoping), warp-uniform vote-break every
//          4 groups. No divergent breaks, no dual-path, no BSSY/BSYNC.
// ---------------------------------------------------------------------------
__global__ void __launch_bounds__(256) fused_kernel(const float* __restrict__ mean,
                                                    const float* __restrict__ cov,
                                                    const float* __restrict__ color,
                                                    const float* __restrict__ alpha,
                                                    const float* __restrict__ depth,
                                                    const float* __restrict__ bg,
                                                    const float* __restrict__ topleft,
                                                    float* __restrict__ out) {
    __shared__ float4 sA[NG+8];        // mx, my, c00', c01'  (aliased by depths in phase 0)
    __shared__ float4 sB[NG+8];        // c11', k', cr, cg
    __shared__ float4 sC4[(NG+8)/4];   // cb, packed
    __shared__ int    sW[8];
    __shared__ int    sRank[4];

    int tid  = threadIdx.x;
    int lane = tid & 31, warp = tid >> 5;

    // tile geometry + background prefetch (hides under barrier wait)
    int bx = blockIdx.x & 15, by = blockIdx.x >> 4;
    float tlx = topleft[0], tly = topleft[1];
    int tx = tid & 15, ty = tid >> 4;
    int pi = ((by*16 + ty)*IMG + bx*16 + tx)*3;
    float bgr = bg[pi+0], bgg = bg[pi+1], bgb = bg[pi+2];

    // ================= Phase 0: prep (4 Gaussians per block) =================
    {
        float4* sd4 = (float4*)sA;              // alias: 1024 depths = 4KB
        const float4* d4g = (const float4*)depth;
        sd4[tid] = d4g[tid];
        if (tid < 4) sRank[tid] = 0;
        __syncthreads();

        int sub = tid >> 6;                     // 0..3 (64 threads per Gaussian)
        int gi  = blockIdx.x*4 + sub;
        float di = ((const float*)sd4)[gi];
        int lo4 = (tid & 63) * 4;               // 16 floats per thread
        int r = 0;
        #pragma unroll
        for (int j4 = 0; j4 < 4; j4++) {
            float4 d = sd4[lo4 + j4];
            int j = (lo4 + j4) * 4;
            r += (d.x < di) || (d.x == di && (j+0) < gi);
            r += (d.y < di) || (d.y == di && (j+1) < gi);
            r += (d.z < di) || (d.z == di && (j+2) < gi);
            r += (d.w < di) || (d.w == di && (j+3) < gi);
        }
        #pragma unroll
        for (int s = 16; s; s >>= 1) r += __shfl_xor_sync(0xffffffffu, r, s);
        if (lane == 0) atomicAdd(&sRank[sub], r);
        __syncthreads();

        if ((tid & 63) == 0) {
            int rank = sRank[sub];
            float a = cov[gi*4+0], b = cov[gi*4+1], c = cov[gi*4+2], d = cov[gi*4+3];
            float det = a*d - b*c;
            const float L2E = 1.4426950408889634f;
            float i00  = d / det;
            float i11  = a / det;
            float ioff = -(b + c) / det;
            float mx = mean[gi*2+0], my = mean[gi*2+1];
            float bs      = 0.5f*(b + c);
            float half_tr = 0.5f*(a + d);
            float disc    = sqrtf(0.25f*(a - d)*(a - d) + bs*bs);
            float al = alpha[gi];
            g_cull[rank] = make_float4(mx, my, QCUT*(half_tr + disc), 0.0f);
            g_q[rank]    = make_float4(-0.5f*L2E*i00, -0.5f*L2E*ioff, -0.5f*L2E*i11,
                                       __log2f(fmaxf(al, 1e-30f)));
            g_c[rank]    = make_float4(color[gi*3+0], color[gi*3+1], color[gi*3+2], 0.0f);
            __threadfence();                    // release this Gaussian's record
        }
        __syncthreads();

        // device-wide barrier (replay-safe; all blocks resident in one wave)
        if (tid == 0) {
            unsigned long long ticket = atomicAdd(&g_bar, 1ULL);
            unsigned long long target = (ticket/NBLK + 1ULL) * NBLK;
            unsigned long long cur;
            do {
                asm volatile("ld.acquire.gpu.global.u64 %0, [%1];"
                             : "=l"(cur) : "l"(&g_bar));
            } while (cur < target);
        }
        __syncthreads();
    }

    // ================= Phase 1: cull + compact (4 Gaussians/thread) ==========
    float x0 = (bx*16 + 0.5f)*PIX - tlx;
    float x1 = (bx*16 + 15.5f)*PIX - tlx;
    float y0 = (by*16 + 0.5f)*PIX - tly;
    float y1 = (by*16 + 15.5f)*PIX - tly;

    int g0 = tid*4;
    float4 cu0 = g_cull[g0+0];
    float4 cu1 = g_cull[g0+1];
    float4 cu2 = g_cull[g0+2];
    float4 cu3 = g_cull[g0+3];
    unsigned m = 0;
    {
        float cx, cy;
        cx = fminf(fmaxf(cu0.x, x0), x1) - cu0.x;
        cy = fminf(fmaxf(cu0.y, y0), y1) - cu0.y;
        if (cx*cx + cy*cy <= cu0.z) m |= 1u;
        cx = fminf(fmaxf(cu1.x, x0), x1) - cu1.x;
        cy = fminf(fmaxf(cu1.y, y0), y1) - cu1.y;
        if (cx*cx + cy*cy <= cu1.z) m |= 2u;
        cx = fminf(fmaxf(cu2.x, x0), x1) - cu2.x;
        cy = fminf(fmaxf(cu2.y, y0), y1) - cu2.y;
        if (cx*cx + cy*cy <= cu2.z) m |= 4u;
        cx = fminf(fmaxf(cu3.x, x0), x1) - cu3.x;
        cy = fminf(fmaxf(cu3.y, y0), y1) - cu3.y;
        if (cx*cx + cy*cy <= cu3.z) m |= 8u;
    }
    int cnt = __popc(m);
    int scan = cnt;
    #pragma unroll
    for (int d = 1; d < 32; d <<= 1) {
        int v = __shfl_up_sync(0xffffffffu, scan, d);
        if (lane >= d) scan += v;
    }
    if (lane == 31) sW[warp] = scan;
    __syncthreads();                             // warp totals
    int4 wv0 = *(const int4*)&sW[0];
    int4 wv1 = *(const int4*)&sW[4];
    int ntot = (wv0.x + wv0.y + wv0.z + wv0.w) + (wv1.x + wv1.y + wv1.z + wv1.w);
    int base = 0;
    if (warp > 0) base += wv0.x;
    if (warp > 1) base += wv0.y;
    if (warp > 2) base += wv0.z;
    if (warp > 3) base += wv0.w;
    if (warp > 4) base += wv1.x;
    if (warp > 5) base += wv1.y;
    if (warp > 6) base += wv1.z;
    int pos = base + (scan - cnt);
    #pragma unroll
    for (int u = 0; u < 4; u++) {
        if (m & (1u << u)) {
            float4 cu = (u == 0) ? cu0 : (u == 1) ? cu1 : (u == 2) ? cu2 : cu3;
            float4 qv = g_q[g0+u];
            float4 cv = g_c[g0+u];
            sA[pos] = make_float4(cu.x, cu.y, qv.x, qv.y);
            sB[pos] = make_float4(qv.z, qv.w, cv.x, cv.y);
            ((float*)sC4)[pos] = cv.z;
            pos++;
        }
    }
    if (tid < 8) {                               // zero-alpha dummies (exact no-op)
        sA[ntot+tid] = make_float4(0.f, 0.f, 0.f, 0.f);
        sB[ntot+tid] = make_float4(0.f, -1e30f, 0.f, 0.f);
        ((float*)sC4)[ntot+tid] = 0.f;
    }
    __syncthreads();                             // list published
    int n = (ntot + 3) & ~3;

    // ================= Phase 2: branch-free composite ========================
    float px = (bx*16 + tx + 0.5f)*PIX - tlx;
    float py = (by*16 + ty + 0.5f)*PIX - tly;

    float T = 1.0f, cr = 0.0f, cg = 0.0f, cb = 0.0f;

    float4 A0 = sA[0], A1 = sA[1], A2 = sA[2], A3 = sA[3];
    float4 B0 = sB[0], B1 = sB[1], B2 = sB[2], B3 = sB[3];
    float4 Cv = sC4[0];

    #pragma unroll 1
    for (int i = 0; i < n; i += 4) {
        float4 nA0 = sA[i+4], nA1 = sA[i+5], nA2 = sA[i+6], nA3 = sA[i+7];
        float4 nB0 = sB[i+4], nB1 = sB[i+5], nB2 = sB[i+6], nB3 = sB[i+7];
        float4 nCv = sC4[i/4 + 1];

        float a0, a1, a2, a3;
        {
            float dx, dy, qd;
            dx = px - A0.x; dy = py - A0.y;
            qd = dx*(A0.z*dx + A0.w*dy) + (B0.x*dy*dy + B0.y);
            a0 = fminf(exp2f(qd), 0.99f);
            dx = px - A1.x; dy = py - A1.y;
            qd = dx*(A1.z*dx + A1.w*dy) + (B1.x*dy*dy + B1.y);
            a1 = fminf(exp2f(qd), 0.99f);
            dx = px - A2.x; dy = py - A2.y;
            qd = dx*(A2.z*dx + A2.w*dy) + (B2.x*dy*dy + B2.y);
            a2 = fminf(exp2f(qd), 0.99f);
            dx = px - A3.x; dy = py - A3.y;
            qd = dx*(A3.z*dx + A3.w*dy) + (B3.x*dy*dy + B3.y);
            a3 = fminf(exp2f(qd), 0.99f);
        }
        // unconditional exclusive-prefix T weights (serial 4-mul chain);
        // post-threshold slop telescopes to <= T_TH absolute — within budget.
        float t0 = T;
        float t1 = t0 * (1.0f - a0);
        float t2 = t1 * (1.0f - a1);
        float t3 = t2 * (1.0f - a2);
        T        = t3 * (1.0f - a3);
        float w0 = a0*t0, w1 = a1*t1, w2 = a2*t2, w3 = a3*t3;
        cr = fmaf(w0, B0.z, cr); cg = fmaf(w0, B0.w, cg); cb = fmaf(w0, Cv.x, cb);
        cr = fmaf(w1, B1.z, cr); cg = fmaf(w1, B1.w, cg); cb = fmaf(w1, Cv.y, cb);
        cr = fmaf(w2, B2.z, cr); cg = fmaf(w2, B2.w, cg); cb = fmaf(w2, Cv.z, cb);
        cr = fmaf(w3, B3.z, cr); cg = fmaf(w3, B3.w, cg); cb = fmaf(w3, Cv.w, cb);

        A0 = nA0; A1 = nA1; A2 = nA2; A3 = nA3;
        B0 = nB0; B1 = nB1; B2 = nB2; B3 = nB3;
        Cv = nCv;

        // warp-uniform termination vote every 4th group (convergent)
        if (((i >> 2) & 3) == 3) {
            if (!__any_sync(0xffffffffu, T > T_TH)) break;
        }
    }

    out[pi+0] = cr + T*bgr;
    out[pi+1] = cg + T*bgg;
    out[pi+2] = cb + T*bgb;
}

extern "C" void kernel_launch(void* const* d_in, const int* in_sizes, int n_in,
                              void* d_out, int out_size) {
    const float* mean    = (const float*)d_in[0];
    const float* cov     = (const float*)d_in[1];
    const float* color   = (const float*)d_in[2];
    const float* alpha   = (const float*)d_in[3];
    const float* depth   = (const float*)d_in[4];
    const float* bg      = (const float*)d_in[5];
    const float* topleft = (const float*)d_in[6];

    fused_kernel<<<NBLK, 256>>>(mean, cov, color, alpha, depth,
                                bg, topleft, (float*)d_out);
}

// round 15
// speedup vs baseline: 1.1359x; 1.0191x over previous
#include <cuda_runtime.h>

#define IMG 256
#define NG 1024
#define PIX (1.0f/256.0f)
#define T_TH 1e-4f
#define QCUT 10.0f   // cull: quad > 10 => contribution < alpha*e^-5 (boundary-only)
#define NBLK 256     // 16 x 16 tiles of 16x16 px; all resident in one wave

// Sorted + packed per-Gaussian data (device scratch, no allocs)
__device__ float4 g_cull[NG];  // mx, my, rad2, pad
__device__ float4 g_q[NG];     // c00', c01', c11', k'
__device__ float4 g_c[NG];     // cr, cg, cb, pad
__device__ unsigned long long g_bar;   // monotonic barrier counter (zero-init)

// ---------------------------------------------------------------------------
// Single fused kernel: 256 blocks x 512 threads (2 blocks/SM, all resident).
// Phase 0: each block preps 4 Gaussians, device-wide barrier (replay-safe).
// Phase 1: per-tile cull+compact of all 1024 sorted Gaussians (2 per thread).
// Phase 2: DEPTH-SPLIT composite: threads p and p+256 composite the front and
//          back halves of the survivor list in parallel (associative combine
//          c = cA + TA*cB, T = TA*TB), halving the worst-tile critical path.
//          Unconditional updates (no masks; same error bound as R14).
// ---------------------------------------------------------------------------
__global__ void __launch_bounds__(512, 2) fused_kernel(const float* __restrict__ mean,
                                                       const float* __restrict__ cov,
                                                       const float* __restrict__ color,
                                                       const float* __restrict__ alpha,
                                                       const float* __restrict__ depth,
                                                       const float* __restrict__ bg,
                                                       const float* __restrict__ topleft,
                                                       float* __restrict__ out) {
    __shared__ float4 sA[NG+16];        // mx, my, c00', c01'  (aliased by depths in phase 0)
    __shared__ float4 sB[NG+16];        // c11', k', cr, cg
    __shared__ float4 sC4[(NG+16)/4];   // cb, packed
    __shared__ float4 sComb[256];       // back-half partial (cr, cg, cb, T)
    __shared__ int    sW[16];
    __shared__ int    sRank[4];

    int tid  = threadIdx.x;
    int lane = tid & 31, warp = tid >> 5;

    // tile geometry
    int bx = blockIdx.x & 15, by = blockIdx.x >> 4;
    float tlx = topleft[0], tly = topleft[1];
    int p  = tid & 255;                 // pixel id within tile
    int tx = p & 15, ty = p >> 4;
    int half = tid >> 8;                // 0 = front segment, 1 = back segment
    int pi = ((by*16 + ty)*IMG + bx*16 + tx)*3;
    float bgr = 0.f, bgg = 0.f, bgb = 0.f;
    if (half == 0) { bgr = bg[pi+0]; bgg = bg[pi+1]; bgb = bg[pi+2]; }

    // ================= Phase 0: prep (4 Gaussians per block) =================
    {
        float4* sd4 = (float4*)sA;              // alias: 1024 depths = 4KB
        const float4* d4g = (const float4*)depth;
        if (tid < 256) sd4[tid] = d4g[tid];
        if (tid < 4)   sRank[tid] = 0;
        __syncthreads();

        if (tid < 256) {
            int sub = tid >> 6;                 // 0..3 (64 threads per Gaussian)
            int gi  = blockIdx.x*4 + sub;
            float di = ((const float*)sd4)[gi];
            int lo4 = (tid & 63) * 4;           // 16 floats per thread
            int r = 0;
            #pragma unroll
            for (int j4 = 0; j4 < 4; j4++) {
                float4 d = sd4[lo4 + j4];
                int j = (lo4 + j4) * 4;
                r += (d.x < di) || (d.x == di && (j+0) < gi);
                r += (d.y < di) || (d.y == di && (j+1) < gi);
                r += (d.z < di) || (d.z == di && (j+2) < gi);
                r += (d.w < di) || (d.w == di && (j+3) < gi);
            }
            #pragma unroll
            for (int s = 16; s; s >>= 1) r += __shfl_xor_sync(0xffffffffu, r, s);
            if (lane == 0) atomicAdd(&sRank[sub], r);
        }
        __syncthreads();

        if (tid < 256 && (tid & 63) == 0) {
            int sub = tid >> 6;
            int gi  = blockIdx.x*4 + sub;
            int rank = sRank[sub];
            float a = cov[gi*4+0], b = cov[gi*4+1], c = cov[gi*4+2], d = cov[gi*4+3];
            float det = a*d - b*c;
            const float L2E = 1.4426950408889634f;
            float i00  = d / det;
            float i11  = a / det;
            float ioff = -(b + c) / det;
            float mx = mean[gi*2+0], my = mean[gi*2+1];
            float bs      = 0.5f*(b + c);
            float half_tr = 0.5f*(a + d);
            float disc    = sqrtf(0.25f*(a - d)*(a - d) + bs*bs);
            float al = alpha[gi];
            g_cull[rank] = make_float4(mx, my, QCUT*(half_tr + disc), 0.0f);
            g_q[rank]    = make_float4(-0.5f*L2E*i00, -0.5f*L2E*ioff, -0.5f*L2E*i11,
                                       __log2f(fmaxf(al, 1e-30f)));
            g_c[rank]    = make_float4(color[gi*3+0], color[gi*3+1], color[gi*3+2], 0.0f);
            __threadfence();                    // release this Gaussian's record
        }
        __syncthreads();

        // device-wide barrier (replay-safe; all blocks resident in one wave)
        if (tid == 0) {
            unsigned long long ticket = atomicAdd(&g_bar, 1ULL);
            unsigned long long target = (ticket/NBLK + 1ULL) * NBLK;
            unsigned long long cur;
            do {
                asm volatile("ld.acquire.gpu.global.u64 %0, [%1];"
                             : "=l"(cur) : "l"(&g_bar));
            } while (cur < target);
        }
        __syncthreads();
    }

    // ================= Phase 1: cull + compact (2 Gaussians/thread) ==========
    float x0 = (bx*16 + 0.5f)*PIX - tlx;
    float x1 = (bx*16 + 15.5f)*PIX - tlx;
    float y0 = (by*16 + 0.5f)*PIX - tly;
    float y1 = (by*16 + 15.5f)*PIX - tly;

    int g0 = tid*2;
    float4 cu0 = g_cull[g0+0];
    float4 cu1 = g_cull[g0+1];
    unsigned m = 0;
    {
        float cx, cy;
        cx = fminf(fmaxf(cu0.x, x0), x1) - cu0.x;
        cy = fminf(fmaxf(cu0.y, y0), y1) - cu0.y;
        if (cx*cx + cy*cy <= cu0.z) m |= 1u;
        cx = fminf(fmaxf(cu1.x, x0), x1) - cu1.x;
        cy = fminf(fmaxf(cu1.y, y0), y1) - cu1.y;
        if (cx*cx + cy*cy <= cu1.z) m |= 2u;
    }
    int cnt = __popc(m);
    int scan = cnt;
    #pragma unroll
    for (int d = 1; d < 32; d <<= 1) {
        int v = __shfl_up_sync(0xffffffffu, scan, d);
        if (lane >= d) scan += v;
    }
    if (lane == 31) sW[warp] = scan;
    __syncthreads();                             // warp totals
    int ntot = 0;
    #pragma unroll
    for (int w = 0; w < 16; w++) ntot += sW[w];
    int base = 0;
    #pragma unroll
    for (int w = 0; w < 15; w++) if (w < warp) base += sW[w];
    int pos = base + (scan - cnt);
    #pragma unroll
    for (int u = 0; u < 2; u++) {
        if (m & (1u << u)) {
            float4 cu = (u == 0) ? cu0 : cu1;
            float4 qv = g_q[g0+u];
            float4 cv = g_c[g0+u];
            sA[pos] = make_float4(cu.x, cu.y, qv.x, qv.y);
            sB[pos] = make_float4(qv.z, qv.w, cv.x, cv.y);
            ((float*)sC4)[pos] = cv.z;
            pos++;
        }
    }
    if (tid < 12) {                              // zero-alpha dummies (exact no-op)
        sA[ntot+tid] = make_float4(0.f, 0.f, 0.f, 0.f);
        sB[ntot+tid] = make_float4(0.f, -1e30f, 0.f, 0.f);
        ((float*)sC4)[ntot+tid] = 0.f;
    }
    __syncthreads();                             // list published
    int n8   = (ntot + 7) & ~7;                  // pad to multiple of 8
    int seg  = n8 >> 1;                          // per-segment length (mult of 4)
    int sbeg = half * seg;
    int send = sbeg + seg;

    // ================= Phase 2: depth-split composite ========================
    float px = (bx*16 + tx + 0.5f)*PIX - tlx;
    float py = (by*16 + ty + 0.5f)*PIX - tly;

    float T = 1.0f, cr = 0.0f, cg = 0.0f, cb = 0.0f;

    float4 A0 = sA[sbeg+0], A1 = sA[sbeg+1], A2 = sA[sbeg+2], A3 = sA[sbeg+3];
    float4 B0 = sB[sbeg+0], B1 = sB[sbeg+1], B2 = sB[sbeg+2], B3 = sB[sbeg+3];
    float4 Cv = sC4[sbeg/4];

    #pragma unroll 1
    for (int i = sbeg; i < send; i += 4) {
        float4 nA0 = sA[i+4], nA1 = sA[i+5], nA2 = sA[i+6], nA3 = sA[i+7];
        float4 nB0 = sB[i+4], nB1 = sB[i+5], nB2 = sB[i+6], nB3 = sB[i+7];
        float4 nCv = sC4[i/4 + 1];

        float a0, a1, a2, a3;
        {
            float dx, dy, qd;
            dx = px - A0.x; dy = py - A0.y;
            qd = dx*(A0.z*dx + A0.w*dy) + (B0.x*dy*dy + B0.y);
            a0 = fminf(exp2f(qd), 0.99f);
            dx = px - A1.x; dy = py - A1.y;
            qd = dx*(A1.z*dx + A1.w*dy) + (B1.x*dy*dy + B1.y);
            a1 = fminf(exp2f(qd), 0.99f);
            dx = px - A2.x; dy = py - A2.y;
            qd = dx*(A2.z*dx + A2.w*dy) + (B2.x*dy*dy + B2.y);
            a2 = fminf(exp2f(qd), 0.99f);
            dx = px - A3.x; dy = py - A3.y;
            qd = dx*(A3.z*dx + A3.w*dy) + (B3.x*dy*dy + B3.y);
            a3 = fminf(exp2f(qd), 0.99f);
        }
        float t0 = T;
        float t1 = t0 * (1.0f - a0);
        float t2 = t1 * (1.0f - a1);
        float t3 = t2 * (1.0f - a2);
        T        = t3 * (1.0f - a3);
        float w0 = a0*t0, w1 = a1*t1, w2 = a2*t2, w3 = a3*t3;
        cr = fmaf(w0, B0.z, cr); cg = fmaf(w0, B0.w, cg); cb = fmaf(w0, Cv.x, cb);
        cr = fmaf(w1, B1.z, cr); cg = fmaf(w1, B1.w, cg); cb = fmaf(w1, Cv.y, cb);
        cr = fmaf(w2, B2.z, cr); cg = fmaf(w2, B2.w, cg); cb = fmaf(w2, Cv.z, cb);
        cr = fmaf(w3, B3.z, cr); cg = fmaf(w3, B3.w, cg); cb = fmaf(w3, Cv.w, cb);

        A0 = nA0; A1 = nA1; A2 = nA2; A3 = nA3;
        B0 = nB0; B1 = nB1; B2 = nB2; B3 = nB3;
        Cv = nCv;

        // warp-uniform termination vote every 4th group (convergent; warps are
        // segment-homogeneous). Remaining contributions bounded by T <= 1e-4.
        if (((i >> 2) & 3) == 3) {
            if (!__any_sync(0xffffffffu, T > T_TH)) break;
        }
    }

    // combine: c = cA + TA*cB, T = TA*TB
    if (half == 1) sComb[p] = make_float4(cr, cg, cb, T);
    __syncthreads();
    if (half == 0) {
        float4 cB2 = sComb[p];
        cr = fmaf(T, cB2.x, cr);
        cg = fmaf(T, cB2.y, cg);
        cb = fmaf(T, cB2.z, cb);
        T  = T * cB2.w;
        out[pi+0] = cr + T*bgr;
        out[pi+1] = cg + T*bgg;
        out[pi+2] = cb + T*bgb;
    }
}

extern "C" void kernel_launch(void* const* d_in, const int* in_sizes, int n_in,
                              void* d_out, int out_size) {
    const float* mean    = (const float*)d_in[0];
    const float* cov     = (const float*)d_in[1];
    const float* color   = (const float*)d_in[2];
    const float* alpha   = (const float*)d_in[3];
    const float* depth   = (const float*)d_in[4];
    const float* bg      = (const float*)d_in[5];
    const float* topleft = (const float*)d_in[6];

    fused_kernel<<<NBLK, 512>>>(mean, cov, color, alpha, depth,
                                bg, topleft, (float*)d_out);
}